// round 3
// baseline (speedup 1.0000x reference)
#include <cuda_runtime.h>
#include <math.h>

#define NN 512
#define MM 2048
#define FEAT 1024
#define GG 16
#define DG 64

// ---------------- scratch (device globals; no allocation) ----------------
__device__ float d_q[NN * FEAT];                    // (q + u) / 8, [n][g*64+d]
__device__ float d_k[MM * FEAT];                    // k, [m][g*64+d]
__device__ float d_v[MM * FEAT];                    // V = ref_feat @ Wv_flat^T, [m][g*64+d]
__device__ float d_logw[(size_t)GG * NN * MM];      // log(relu(Wg.pe)+1e-6), [g][n][m]
__device__ float4 d_roip[NN];                       // cx, cy, w, h
__device__ float4 d_refp[MM];

// ---------------- box param prep ----------------
__global__ void prep_boxes_kernel(const float* __restrict__ bbox,
                                  const float* __restrict__ refb)
{
    int i = blockIdx.x * 256 + threadIdx.x;
    if (i < NN) {
        float x0 = bbox[i*4+0], y0 = bbox[i*4+1], x1 = bbox[i*4+2], y1 = bbox[i*4+3];
        d_roip[i] = make_float4(0.5f*(x0+x1), 0.5f*(y0+y1), x1 - x0 + 1.0f, y1 - y0 + 1.0f);
    }
    if (i < MM) {
        float x0 = refb[i*4+0], y0 = refb[i*4+1], x1 = refb[i*4+2], y1 = refb[i*4+3];
        d_refp[i] = make_float4(0.5f*(x0+x1), 0.5f*(y0+y1), x1 - x0 + 1.0f, y1 - y0 + 1.0f);
    }
}

// ---------------- position-embedding prior:  logw[g][n][m] ----------------
__global__ __launch_bounds__(128)
void logw_kernel(const float* __restrict__ Wg_w, const float* __restrict__ Wg_b)
{
    __shared__ float wg[GG * 64];
    __shared__ float wgb[GG];
    int n = blockIdx.y;
    int m = blockIdx.x * 128 + threadIdx.x;
    for (int t = threadIdx.x; t < GG * 64; t += 128) wg[t] = Wg_w[t];
    if (threadIdx.x < GG) wgb[threadIdx.x] = Wg_b[threadIdx.x];
    float4 rp = d_roip[n];
    float4 fp = d_refp[m];
    __syncthreads();

    float pos[4];
    pos[0] = logf(fabsf((rp.x - fp.x) / rp.z) + 1e-3f);
    pos[1] = logf(fabsf((rp.y - fp.y) / rp.w) + 1e-3f);
    pos[2] = logf(rp.z / fp.z);
    pos[3] = logf(rp.w / fp.w);

    // dim_mat = 1000^(f/8), f=0..7 (correctly rounded fp32)
    const float dm[8] = {1.0f, 2.3713737f, 5.6234131f, 13.335214f,
                         31.622776f, 74.989420f, 177.82794f, 421.69650f};
    float emb[64];
#pragma unroll
    for (int i = 0; i < 4; i++) {
        float p100 = pos[i] * 100.0f;
#pragma unroll
        for (int f = 0; f < 8; f++) {
            float x = p100 / dm[f];
            float s, c;
            sincosf(x, &s, &c);
            emb[i*16 + f]     = s;
            emb[i*16 + 8 + f] = c;
        }
    }
    size_t base = (size_t)n * MM + m;
#pragma unroll 1
    for (int g = 0; g < GG; g++) {
        float a = wgb[g];
#pragma unroll
        for (int e = 0; e < 64; e++) a += wg[g*64 + e] * emb[e];
        a = fmaxf(a, 0.0f) + 1e-6f;
        d_logw[(size_t)g * NN * MM + base] = logf(a);
    }
}

// ---------------- generic NT SGEMM: C[r][o] = (A[r,:].B[o,:] + bias + bias2)*scale ----
__global__ __launch_bounds__(256)
void sgemm_nt_kernel(const float* __restrict__ A, const float* __restrict__ B,
                     const float* __restrict__ bias, const float* __restrict__ bias2,
                     float scale, float* __restrict__ C, int R, int O, int K)
{
    __shared__ float As[8][128];
    __shared__ float Bs[8][128];
    int br = blockIdx.y * 128;
    int bo = blockIdx.x * 128;
    int tid = threadIdx.x;
    int lr = tid >> 1;
    int lc = (tid & 1) * 4;
    int tx = tid & 15;
    int ty = tid >> 4;
    const float* Ap = A + (size_t)(br + lr) * K + lc;
    const float* Bp = B + (size_t)(bo + lr) * K + lc;

    float acc[8][8];
#pragma unroll
    for (int i = 0; i < 8; i++)
#pragma unroll
        for (int j = 0; j < 8; j++) acc[i][j] = 0.0f;

    for (int k0 = 0; k0 < K; k0 += 8) {
        float4 a4 = *(const float4*)(Ap + k0);
        float4 b4 = *(const float4*)(Bp + k0);
        As[lc+0][lr] = a4.x; As[lc+1][lr] = a4.y; As[lc+2][lr] = a4.z; As[lc+3][lr] = a4.w;
        Bs[lc+0][lr] = b4.x; Bs[lc+1][lr] = b4.y; Bs[lc+2][lr] = b4.z; Bs[lc+3][lr] = b4.w;
        __syncthreads();
#pragma unroll
        for (int kk = 0; kk < 8; kk++) {
            float ra[8], rb[8];
            *(float4*)&ra[0] = *(const float4*)&As[kk][ty*8];
            *(float4*)&ra[4] = *(const float4*)&As[kk][ty*8 + 4];
            *(float4*)&rb[0] = *(const float4*)&Bs[kk][tx*8];
            *(float4*)&rb[4] = *(const float4*)&Bs[kk][tx*8 + 4];
#pragma unroll
            for (int i = 0; i < 8; i++)
#pragma unroll
                for (int j = 0; j < 8; j++) acc[i][j] += ra[i] * rb[j];
        }
        __syncthreads();
    }
#pragma unroll
    for (int i = 0; i < 8; i++) {
        int r = br + ty*8 + i;
#pragma unroll
        for (int j = 0; j < 8; j++) {
            int o = bo + tx*8 + j;
            float v = acc[i][j];
            if (bias)  v += bias[o];
            if (bias2) v += bias2[o];
            C[(size_t)r * O + o] = v * scale;
        }
    }
}

// ---------------- fused flash attention + V contraction ----------------
// grid (NN/64, GG), 256 threads, 64-wide m tiles. Dynamic smem = 4*64*64 floats.
__global__ __launch_bounds__(256)
void attn_kernel(const float* __restrict__ Wv_b, float* __restrict__ out)
{
    extern __shared__ float sm[];
    float* Qs  = sm;            // [d][n]  (transposed)
    float* KVs = sm + 4096;     // K: [d][m] (transposed); later V: [m][d]
    float* Ls  = sm + 8192;     // logw tile [n][m]
    float* Ps  = sm + 12288;    // logits/probs [m][n]
    __shared__ float rmax[64], rsum[64], rfac[64];

    int g  = blockIdx.y;
    int n0 = blockIdx.x * 64;
    int tid = threadIdx.x;
    int tx = tid & 15, ty = tid >> 4;

    // load Q tile, transpose to [d][n]
    for (int idx = tid; idx < 64 * 16; idx += 256) {
        int n = idx >> 4, c4 = (idx & 15) * 4;
        float4 v = *(const float4*)&d_q[(size_t)(n0 + n) * FEAT + g*64 + c4];
        Qs[(c4+0)*64 + n] = v.x; Qs[(c4+1)*64 + n] = v.y;
        Qs[(c4+2)*64 + n] = v.z; Qs[(c4+3)*64 + n] = v.w;
    }
    if (tid < 64) { rmax[tid] = -1e30f; rsum[tid] = 0.0f; }

    float accO[4][4];
#pragma unroll
    for (int i = 0; i < 4; i++)
#pragma unroll
        for (int j = 0; j < 4; j++) accO[i][j] = 0.0f;
    __syncthreads();

    for (int m0 = 0; m0 < MM; m0 += 64) {
        // K tile transposed to [d][m]
        for (int idx = tid; idx < 64 * 16; idx += 256) {
            int mm = idx >> 4, c4 = (idx & 15) * 4;
            float4 v = *(const float4*)&d_k[(size_t)(m0 + mm) * FEAT + g*64 + c4];
            KVs[(c4+0)*64 + mm] = v.x; KVs[(c4+1)*64 + mm] = v.y;
            KVs[(c4+2)*64 + mm] = v.z; KVs[(c4+3)*64 + mm] = v.w;
        }
        // logw tile, straight copy [n][m]
        for (int idx = tid; idx < 64 * 16; idx += 256) {
            int n = idx >> 4, c4 = (idx & 15) * 4;
            *(float4*)&Ls[n*64 + c4] =
                *(const float4*)&d_logw[((size_t)g * NN + (n0 + n)) * MM + m0 + c4];
        }
        __syncthreads();

        // S = Qs^T Ks  (each thread 4x4)
        float s[4][4];
#pragma unroll
        for (int i = 0; i < 4; i++)
#pragma unroll
            for (int j = 0; j < 4; j++) s[i][j] = 0.0f;
#pragma unroll 16
        for (int d = 0; d < 64; d++) {
            float qr[4], kr[4];
            *(float4*)qr = *(const float4*)&Qs[d*64 + ty*4];
            *(float4*)kr = *(const float4*)&KVs[d*64 + tx*4];
#pragma unroll
            for (int i = 0; i < 4; i++)
#pragma unroll
                for (int j = 0; j < 4; j++) s[i][j] += qr[i] * kr[j];
        }
        // + logw, store logits transposed: Ps[m][n]
#pragma unroll
        for (int i = 0; i < 4; i++)
#pragma unroll
            for (int j = 0; j < 4; j++)
                Ps[(tx*4 + j)*64 + (ty*4 + i)] = s[i][j] + Ls[(ty*4 + i)*64 + tx*4 + j];
        __syncthreads();

        // online softmax (threads 0..63, one row each) ...
        if (tid < 64) {
            float om = rmax[tid];
            float nm = om;
#pragma unroll 8
            for (int mv = 0; mv < 64; mv++) nm = fmaxf(nm, Ps[mv*64 + tid]);
            float fac = __expf(om - nm);
            float sum = 0.0f;
#pragma unroll 8
            for (int mv = 0; mv < 64; mv++) {
                float p = __expf(Ps[mv*64 + tid] - nm);
                Ps[mv*64 + tid] = p;
                sum += p;
            }
            rmax[tid] = nm;
            rsum[tid] = rsum[tid] * fac + sum;
            rfac[tid] = fac;
        }
        // ... while all threads stream V into the (now free) K buffer, natural [m][d]
        for (int idx = tid; idx < 64 * 16; idx += 256) {
            int mm = idx >> 4, c4 = (idx & 15) * 4;
            *(float4*)&KVs[mm*64 + c4] =
                *(const float4*)&d_v[(size_t)(m0 + mm) * FEAT + g*64 + c4];
        }
        __syncthreads();

        // rescale accumulators, then O += P^T V
        float fi[4];
#pragma unroll
        for (int i = 0; i < 4; i++) fi[i] = rfac[ty*4 + i];
#pragma unroll
        for (int i = 0; i < 4; i++)
#pragma unroll
            for (int j = 0; j < 4; j++) accO[i][j] *= fi[i];
#pragma unroll 16
        for (int mm = 0; mm < 64; mm++) {
            float pr[4], vr[4];
            *(float4*)pr = *(const float4*)&Ps[mm*64 + ty*4];
            *(float4*)vr = *(const float4*)&KVs[mm*64 + tx*4];
#pragma unroll
            for (int i = 0; i < 4; i++)
#pragma unroll
                for (int j = 0; j < 4; j++) accO[i][j] += pr[i] * vr[j];
        }
        __syncthreads();
    }

    // epilogue: divide by softmax denominator, add Wv_b, write out
#pragma unroll
    for (int i = 0; i < 4; i++) {
        int n = n0 + ty*4 + i;
        float inv = 1.0f / rsum[ty*4 + i];
#pragma unroll
        for (int j = 0; j < 4; j++) {
            int o = g*64 + tx*4 + j;
            out[(size_t)n * FEAT + o] = accO[i][j] * inv + Wv_b[o];
        }
    }
}

// ---------------- launch ----------------
extern "C" void kernel_launch(void* const* d_in, const int* in_sizes, int n_in,
                              void* d_out, int out_size)
{
    const float* bbox     = (const float*)d_in[0];
    const float* ref_bbox = (const float*)d_in[1];
    const float* roi_feat = (const float*)d_in[2];
    const float* ref_feat = (const float*)d_in[3];
    const float* Wg_w     = (const float*)d_in[4];
    const float* Wg_b     = (const float*)d_in[5];
    const float* Wq_w     = (const float*)d_in[6];
    const float* Wq_b     = (const float*)d_in[7];
    const float* Wk_w     = (const float*)d_in[8];
    const float* Wk_b     = (const float*)d_in[9];
    const float* Wv_w     = (const float*)d_in[10];   // [G,DG,FEAT] == flat [1024,1024]
    const float* Wv_b     = (const float*)d_in[11];
    const float* u        = (const float*)d_in[12];   // [G,1,64] == flat [1024]
    float* out = (float*)d_out;

    (void)in_sizes; (void)n_in; (void)out_size;

    cudaFuncSetAttribute(attn_kernel, cudaFuncAttributeMaxDynamicSharedMemorySize, 65536);

    float *qp, *kp, *vp;
    cudaGetSymbolAddress((void**)&qp, d_q);
    cudaGetSymbolAddress((void**)&kp, d_k);
    cudaGetSymbolAddress((void**)&vp, d_v);

    prep_boxes_kernel<<<8, 256>>>(bbox, ref_bbox);
    logw_kernel<<<dim3(MM / 128, NN), 128>>>(Wg_w, Wg_b);

    // q = (roi @ Wq^T + Wq_b + u) * 0.125   (folds content bias u and 1/sqrt(64))
    sgemm_nt_kernel<<<dim3(FEAT/128, NN/128), 256>>>(roi_feat, Wq_w, Wq_b, u, 0.125f,
                                                     qp, NN, FEAT, FEAT);
    // k = ref @ Wk^T + Wk_b
    sgemm_nt_kernel<<<dim3(FEAT/128, MM/128), 256>>>(ref_feat, Wk_w, Wk_b, nullptr, 1.0f,
                                                     kp, MM, FEAT, FEAT);
    // V = ref @ Wv_flat^T   (Wv_b added in attention epilogue)
    sgemm_nt_kernel<<<dim3(FEAT/128, MM/128), 256>>>(ref_feat, Wv_w, nullptr, nullptr, 1.0f,
                                                     vp, MM, FEAT, FEAT);

    attn_kernel<<<dim3(NN/64, GG), 256, 65536>>>(Wv_b, out);
}

// round 4
// speedup vs baseline: 2.3506x; 2.3506x over previous
#include <cuda_runtime.h>
#include <math.h>
#include <stdint.h>

#define NN 512
#define MM 2048
#define FEAT 1024
#define GG 16
#define DG 64

// ---------------- scratch (device globals; no allocation) ----------------
__device__ float d_q[NN * FEAT];                    // (q + u) / 8, [n][g*64+d]
__device__ float d_k[MM * FEAT];                    // k, [m][g*64+d]
__device__ float d_v[MM * FEAT];                    // V = ref_feat @ Wv_flat^T, [m][g*64+d]
__device__ float d_logw[(size_t)GG * NN * MM];      // log(relu(Wg.pe)+1e-6), [g][n][m]
__device__ float4 d_roip[NN];                       // cx, cy, w, h
__device__ float4 d_refp[MM];

// ---------------- tf32 helpers ----------------
__device__ __forceinline__ float tf32r(float x) {
    uint32_t u;
    asm("cvt.rna.tf32.f32 %0, %1;" : "=r"(u) : "f"(x));
    return __uint_as_float(u);
}
__device__ __forceinline__ void mma8(float* c, const uint32_t* a, const uint32_t* b) {
    asm volatile(
        "mma.sync.aligned.m16n8k8.row.col.f32.tf32.tf32.f32 "
        "{%0,%1,%2,%3}, {%4,%5,%6,%7}, {%8,%9}, {%0,%1,%2,%3};"
        : "+f"(c[0]), "+f"(c[1]), "+f"(c[2]), "+f"(c[3])
        : "r"(a[0]), "r"(a[1]), "r"(a[2]), "r"(a[3]), "r"(b[0]), "r"(b[1]));
}
__device__ __forceinline__ void st4tf(float* p, float4 v) {
    *(float4*)p = make_float4(tf32r(v.x), tf32r(v.y), tf32r(v.z), tf32r(v.w));
}

// ---------------- box param prep ----------------
__global__ void prep_boxes_kernel(const float* __restrict__ bbox,
                                  const float* __restrict__ refb)
{
    int i = blockIdx.x * 256 + threadIdx.x;
    if (i < NN) {
        float x0 = bbox[i*4+0], y0 = bbox[i*4+1], x1 = bbox[i*4+2], y1 = bbox[i*4+3];
        d_roip[i] = make_float4(0.5f*(x0+x1), 0.5f*(y0+y1), x1 - x0 + 1.0f, y1 - y0 + 1.0f);
    }
    if (i < MM) {
        float x0 = refb[i*4+0], y0 = refb[i*4+1], x1 = refb[i*4+2], y1 = refb[i*4+3];
        d_refp[i] = make_float4(0.5f*(x0+x1), 0.5f*(y0+y1), x1 - x0 + 1.0f, y1 - y0 + 1.0f);
    }
}

// ---------------- position-embedding prior:  logw[g][n][m] ----------------
__global__ __launch_bounds__(128)
void logw_kernel(const float* __restrict__ Wg_w, const float* __restrict__ Wg_b)
{
    __shared__ float wg[GG * 64];
    __shared__ float wgb[GG];
    int n = blockIdx.y;
    int m = blockIdx.x * 128 + threadIdx.x;
    for (int t = threadIdx.x; t < GG * 64; t += 128) wg[t] = Wg_w[t];
    if (threadIdx.x < GG) wgb[threadIdx.x] = Wg_b[threadIdx.x];
    float4 rp = d_roip[n];
    float4 fp = d_refp[m];
    __syncthreads();

    float pos[4];
    pos[0] = logf(fabsf((rp.x - fp.x) / rp.z) + 1e-3f);
    pos[1] = logf(fabsf((rp.y - fp.y) / rp.w) + 1e-3f);
    pos[2] = logf(rp.z / fp.z);
    pos[3] = logf(rp.w / fp.w);

    const float dm[8] = {1.0f, 2.3713737f, 5.6234131f, 13.335214f,
                         31.622776f, 74.989420f, 177.82794f, 421.69650f};
    float emb[64];
#pragma unroll
    for (int i = 0; i < 4; i++) {
        float p100 = pos[i] * 100.0f;
#pragma unroll
        for (int f = 0; f < 8; f++) {
            float x = p100 / dm[f];
            float s, c;
            sincosf(x, &s, &c);
            emb[i*16 + f]     = s;
            emb[i*16 + 8 + f] = c;
        }
    }
    size_t base = (size_t)n * MM + m;
#pragma unroll 1
    for (int g = 0; g < GG; g++) {
        float a = wgb[g];
#pragma unroll
        for (int e = 0; e < 64; e++) a += wg[g*64 + e] * emb[e];
        a = fmaxf(a, 0.0f) + 1e-6f;
        d_logw[(size_t)g * NN * MM + base] = logf(a);
    }
}

// ---------------- tf32 tensor-core NT GEMM ----------------
// C[r][o] = (sum_k A[r,k]*B[o,k] + bias[o] + bias2[o]) * scale
// 128x128 block tile, BK=16, 8 warps each computing 64x32.
__global__ __launch_bounds__(256, 2)
void gemm_tf32_nt(const float* __restrict__ A, const float* __restrict__ B,
                  const float* __restrict__ bias, const float* __restrict__ bias2,
                  float scale, float* __restrict__ C, int R, int O, int K)
{
    __shared__ __align__(16) float As[128][20];
    __shared__ __align__(16) float Bs[128][20];
    int tid = threadIdx.x;
    int wid = tid >> 5, lane = tid & 31;
    int gr = lane >> 2, t = lane & 3;
    int wm = (wid >> 2) * 64;     // 0 or 64
    int wn = (wid & 3) * 32;      // 0,32,64,96
    int br = blockIdx.y * 128, bo = blockIdx.x * 128;

    int lr = tid >> 2;            // 0..63
    int lc = (tid & 3) * 4;       // 0,4,8,12
    const float* Ap = A + (size_t)(br + lr) * K + lc;
    const float* Bp = B + (size_t)(bo + lr) * K + lc;
    size_t rstep = (size_t)64 * K;

    float c[4][4][4];
#pragma unroll
    for (int i = 0; i < 4; i++)
#pragma unroll
        for (int j = 0; j < 4; j++)
#pragma unroll
            for (int q = 0; q < 4; q++) c[i][j][q] = 0.0f;

    float4 pa0 = *(const float4*)(Ap);
    float4 pa1 = *(const float4*)(Ap + rstep);
    float4 pb0 = *(const float4*)(Bp);
    float4 pb1 = *(const float4*)(Bp + rstep);

    for (int k0 = 0; k0 < K; k0 += 16) {
        st4tf(&As[lr][lc], pa0);
        st4tf(&As[lr + 64][lc], pa1);
        st4tf(&Bs[lr][lc], pb0);
        st4tf(&Bs[lr + 64][lc], pb1);
        __syncthreads();
        if (k0 + 16 < K) {
            pa0 = *(const float4*)(Ap + k0 + 16);
            pa1 = *(const float4*)(Ap + rstep + k0 + 16);
            pb0 = *(const float4*)(Bp + k0 + 16);
            pb1 = *(const float4*)(Bp + rstep + k0 + 16);
        }
#pragma unroll
        for (int ks = 0; ks < 16; ks += 8) {
            uint32_t a[4][4], b[4][2];
#pragma unroll
            for (int mt = 0; mt < 4; mt++) {
                a[mt][0] = __float_as_uint(As[wm + mt*16 + gr    ][ks + t    ]);
                a[mt][1] = __float_as_uint(As[wm + mt*16 + gr + 8][ks + t    ]);
                a[mt][2] = __float_as_uint(As[wm + mt*16 + gr    ][ks + t + 4]);
                a[mt][3] = __float_as_uint(As[wm + mt*16 + gr + 8][ks + t + 4]);
            }
#pragma unroll
            for (int nt = 0; nt < 4; nt++) {
                b[nt][0] = __float_as_uint(Bs[wn + nt*8 + gr][ks + t    ]);
                b[nt][1] = __float_as_uint(Bs[wn + nt*8 + gr][ks + t + 4]);
            }
#pragma unroll
            for (int mt = 0; mt < 4; mt++)
#pragma unroll
                for (int nt = 0; nt < 4; nt++) mma8(c[mt][nt], a[mt], b[nt]);
        }
        __syncthreads();
    }

#pragma unroll
    for (int mt = 0; mt < 4; mt++) {
        int r0 = br + wm + mt*16 + gr;
#pragma unroll
        for (int nt = 0; nt < 4; nt++) {
            int o = bo + wn + nt*8 + 2*t;
            float v0 = c[mt][nt][0], v1 = c[mt][nt][1];
            float v2 = c[mt][nt][2], v3 = c[mt][nt][3];
            if (bias)  { float b0 = bias[o],  b1 = bias[o+1];  v0 += b0; v2 += b0; v1 += b1; v3 += b1; }
            if (bias2) { float b0 = bias2[o], b1 = bias2[o+1]; v0 += b0; v2 += b0; v1 += b1; v3 += b1; }
            *(float2*)&C[(size_t)r0 * O + o]       = make_float2(v0*scale, v1*scale);
            *(float2*)&C[(size_t)(r0 + 8) * O + o] = make_float2(v2*scale, v3*scale);
        }
    }
}

// ---------------- fused mma flash attention + V contraction ----------------
// grid (NN/64, GG), 128 threads (4 warps). Warp w owns rows w*16..w*16+15 end-to-end:
// softmax stats live in registers (quad shuffles), P round-trips through a
// warp-private smem slice, so only 2 block barriers per 64-wide m tile.
#define ST 68   // stride for Qs/Ks/Ps/Ls (row-indexed frags conflict-free)
#define SV 72   // stride for Vs (k-indexed frags conflict-free)
__global__ __launch_bounds__(128)
void attn_mma_kernel(const float* __restrict__ Wv_b, float* __restrict__ out)
{
    extern __shared__ __align__(16) float sm[];
    float* Qs = sm;                 // [64][68]
    float* Ks = Qs + 64 * ST;       // [64][68]
    float* Ps = Ks + 64 * ST;       // [64][68]
    float* Ls = Ps + 64 * ST;       // [64][68]
    float* Vs = Ls + 64 * ST;       // [64][72]

    int g = blockIdx.y, n0 = blockIdx.x * 64;
    int tid = threadIdx.x, wid = tid >> 5, lane = tid & 31;
    int gr = lane >> 2, t = lane & 3;
    int w16 = wid * 16;
    int row0 = w16 + gr, row1 = w16 + gr + 8;

    // load Q tile (cvt to tf32)
    for (int idx = tid; idx < 64 * 16; idx += 128) {
        int n = idx >> 4, c4 = (idx & 15) * 4;
        float4 v = *(const float4*)&d_q[(size_t)(n0 + n) * FEAT + g*64 + c4];
        st4tf(&Qs[n*ST + c4], v);
    }

    float accO[8][4];
#pragma unroll
    for (int i = 0; i < 8; i++)
#pragma unroll
        for (int j = 0; j < 4; j++) accO[i][j] = 0.0f;
    float rmax0 = -1e30f, rmax1 = -1e30f, rsum0 = 0.0f, rsum1 = 0.0f;

    for (int m0 = 0; m0 < MM; m0 += 64) {
        // K,V: [m][d] ; L: [n][m]
        for (int idx = tid; idx < 64 * 16; idx += 128) {
            int r = idx >> 4, c4 = (idx & 15) * 4;
            float4 kv = *(const float4*)&d_k[(size_t)(m0 + r) * FEAT + g*64 + c4];
            st4tf(&Ks[r*ST + c4], kv);
            float4 vv = *(const float4*)&d_v[(size_t)(m0 + r) * FEAT + g*64 + c4];
            st4tf(&Vs[r*SV + c4], vv);
            *(float4*)&Ls[r*ST + c4] =
                *(const float4*)&d_logw[((size_t)g * NN + (n0 + r)) * MM + m0 + c4];
        }
        __syncthreads();

        // S = Q K^T  (warp tile 16x64)
        float s[8][4];
#pragma unroll
        for (int i = 0; i < 8; i++)
#pragma unroll
            for (int j = 0; j < 4; j++) s[i][j] = 0.0f;
#pragma unroll
        for (int ks = 0; ks < 64; ks += 8) {
            uint32_t a[4];
            a[0] = __float_as_uint(Qs[row0*ST + ks + t    ]);
            a[1] = __float_as_uint(Qs[row1*ST + ks + t    ]);
            a[2] = __float_as_uint(Qs[row0*ST + ks + t + 4]);
            a[3] = __float_as_uint(Qs[row1*ST + ks + t + 4]);
#pragma unroll
            for (int nt = 0; nt < 8; nt++) {
                uint32_t b[2];
                b[0] = __float_as_uint(Ks[(nt*8 + gr)*ST + ks + t    ]);
                b[1] = __float_as_uint(Ks[(nt*8 + gr)*ST + ks + t + 4]);
                mma8(s[nt], a, b);
            }
        }
        // + logw
#pragma unroll
        for (int nt = 0; nt < 8; nt++) {
            int c0 = nt*8 + 2*t;
            float2 l0 = *(const float2*)&Ls[row0*ST + c0];
            float2 l1 = *(const float2*)&Ls[row1*ST + c0];
            s[nt][0] += l0.x; s[nt][1] += l0.y;
            s[nt][2] += l1.x; s[nt][3] += l1.y;
        }
        // online softmax, rows fully warp-local
        float m0v = rmax0, m1v = rmax1;
#pragma unroll
        for (int nt = 0; nt < 8; nt++) {
            m0v = fmaxf(m0v, fmaxf(s[nt][0], s[nt][1]));
            m1v = fmaxf(m1v, fmaxf(s[nt][2], s[nt][3]));
        }
        m0v = fmaxf(m0v, __shfl_xor_sync(0xffffffffu, m0v, 1));
        m0v = fmaxf(m0v, __shfl_xor_sync(0xffffffffu, m0v, 2));
        m1v = fmaxf(m1v, __shfl_xor_sync(0xffffffffu, m1v, 1));
        m1v = fmaxf(m1v, __shfl_xor_sync(0xffffffffu, m1v, 2));
        float fac0 = __expf(rmax0 - m0v), fac1 = __expf(rmax1 - m1v);
        rmax0 = m0v; rmax1 = m1v;
        float sum0 = 0.0f, sum1 = 0.0f;
#pragma unroll
        for (int nt = 0; nt < 8; nt++) {
            int c0 = nt*8 + 2*t;
            float p0 = __expf(s[nt][0] - m0v);
            float p1 = __expf(s[nt][1] - m0v);
            float p2 = __expf(s[nt][2] - m1v);
            float p3 = __expf(s[nt][3] - m1v);
            sum0 += p0 + p1; sum1 += p2 + p3;
            *(float2*)&Ps[row0*ST + c0] = make_float2(tf32r(p0), tf32r(p1));
            *(float2*)&Ps[row1*ST + c0] = make_float2(tf32r(p2), tf32r(p3));
        }
        sum0 += __shfl_xor_sync(0xffffffffu, sum0, 1);
        sum0 += __shfl_xor_sync(0xffffffffu, sum0, 2);
        sum1 += __shfl_xor_sync(0xffffffffu, sum1, 1);
        sum1 += __shfl_xor_sync(0xffffffffu, sum1, 2);
        rsum0 = rsum0 * fac0 + sum0;
        rsum1 = rsum1 * fac1 + sum1;
#pragma unroll
        for (int dt = 0; dt < 8; dt++) {
            accO[dt][0] *= fac0; accO[dt][1] *= fac0;
            accO[dt][2] *= fac1; accO[dt][3] *= fac1;
        }
        __syncwarp();

        // O += P V   (P rows warp-private; V shared)
#pragma unroll
        for (int ks = 0; ks < 64; ks += 8) {
            uint32_t a[4];
            a[0] = __float_as_uint(Ps[row0*ST + ks + t    ]);
            a[1] = __float_as_uint(Ps[row1*ST + ks + t    ]);
            a[2] = __float_as_uint(Ps[row0*ST + ks + t + 4]);
            a[3] = __float_as_uint(Ps[row1*ST + ks + t + 4]);
#pragma unroll
            for (int dt = 0; dt < 8; dt++) {
                uint32_t b[2];
                b[0] = __float_as_uint(Vs[(ks + t    )*SV + dt*8 + gr]);
                b[1] = __float_as_uint(Vs[(ks + t + 4)*SV + dt*8 + gr]);
                mma8(accO[dt], a, b);
            }
        }
        __syncthreads();
    }

    // epilogue
    float i0 = 1.0f / rsum0, i1 = 1.0f / rsum1;
#pragma unroll
    for (int dt = 0; dt < 8; dt++) {
        int o = g*64 + dt*8 + 2*t;
        float b0 = Wv_b[o], b1 = Wv_b[o+1];
        *(float2*)&out[(size_t)(n0 + row0) * FEAT + o] =
            make_float2(accO[dt][0]*i0 + b0, accO[dt][1]*i0 + b1);
        *(float2*)&out[(size_t)(n0 + row1) * FEAT + o] =
            make_float2(accO[dt][2]*i1 + b0, accO[dt][3]*i1 + b1);
    }
}

// ---------------- launch ----------------
extern "C" void kernel_launch(void* const* d_in, const int* in_sizes, int n_in,
                              void* d_out, int out_size)
{
    const float* bbox     = (const float*)d_in[0];
    const float* ref_bbox = (const float*)d_in[1];
    const float* roi_feat = (const float*)d_in[2];
    const float* ref_feat = (const float*)d_in[3];
    const float* Wg_w     = (const float*)d_in[4];
    const float* Wg_b     = (const float*)d_in[5];
    const float* Wq_w     = (const float*)d_in[6];
    const float* Wq_b     = (const float*)d_in[7];
    const float* Wk_w     = (const float*)d_in[8];
    const float* Wk_b     = (const float*)d_in[9];
    const float* Wv_w     = (const float*)d_in[10];   // [G,DG,FEAT] == flat [1024,1024]
    const float* Wv_b     = (const float*)d_in[11];
    const float* u        = (const float*)d_in[12];   // [G,1,64] == flat [1024]
    float* out = (float*)d_out;

    (void)in_sizes; (void)n_in; (void)out_size;

    static const int ATTN_SMEM = (4 * 64 * ST + 64 * SV) * 4;
    cudaFuncSetAttribute(attn_mma_kernel, cudaFuncAttributeMaxDynamicSharedMemorySize, ATTN_SMEM);

    float *qp, *kp, *vp;
    cudaGetSymbolAddress((void**)&qp, d_q);
    cudaGetSymbolAddress((void**)&kp, d_k);
    cudaGetSymbolAddress((void**)&vp, d_v);

    prep_boxes_kernel<<<8, 256>>>(bbox, ref_bbox);
    logw_kernel<<<dim3(MM / 128, NN), 128>>>(Wg_w, Wg_b);

    // q = (roi @ Wq^T + Wq_b + u) * 0.125
    gemm_tf32_nt<<<dim3(FEAT/128, NN/128), 256>>>(roi_feat, Wq_w, Wq_b, u, 0.125f,
                                                  qp, NN, FEAT, FEAT);
    // k = ref @ Wk^T + Wk_b
    gemm_tf32_nt<<<dim3(FEAT/128, MM/128), 256>>>(ref_feat, Wk_w, Wk_b, nullptr, 1.0f,
                                                  kp, MM, FEAT, FEAT);
    // V = ref @ Wv_flat^T
    gemm_tf32_nt<<<dim3(FEAT/128, MM/128), 256>>>(ref_feat, Wv_w, nullptr, nullptr, 1.0f,
                                                  vp, MM, FEAT, FEAT);

    attn_mma_kernel<<<dim3(NN/64, GG), 128, ATTN_SMEM>>>(Wv_b, out);
}

// round 5
// speedup vs baseline: 3.9185x; 1.6670x over previous
#include <cuda_runtime.h>
#include <math.h>
#include <stdint.h>

#define NN 512
#define MM 2048
#define FEAT 1024
#define GG 16
#define DG 64
#define NSPLIT 4

// ---------------- scratch (device globals; no allocation) ----------------
__device__ float d_q[NN * FEAT];                      // (q + u)/8, tf32-rounded
__device__ float d_k[MM * FEAT];                      // k, tf32-rounded
__device__ float d_v[MM * FEAT];                      // V = ref_feat @ Wv^T, tf32-rounded
__device__ float d_logw[(size_t)GG * NN * MM];        // log(relu(Wg.pe)+1e-6)
__device__ float4 d_roip[NN];
__device__ float4 d_refp[MM];
__device__ float  d_po[(size_t)NSPLIT * NN * FEAT];   // unnormalized partial O
__device__ float2 d_pstat[NSPLIT * GG * NN];          // (running max, running sum)

// ---------------- helpers ----------------
__device__ __forceinline__ float tf32r(float x) {
    uint32_t u;
    asm("cvt.rna.tf32.f32 %0, %1;" : "=r"(u) : "f"(x));
    return __uint_as_float(u);
}
__device__ __forceinline__ void mma8(float* c, const uint32_t* a, const uint32_t* b) {
    asm volatile(
        "mma.sync.aligned.m16n8k8.row.col.f32.tf32.tf32.f32 "
        "{%0,%1,%2,%3}, {%4,%5,%6,%7}, {%8,%9}, {%0,%1,%2,%3};"
        : "+f"(c[0]), "+f"(c[1]), "+f"(c[2]), "+f"(c[3])
        : "r"(a[0]), "r"(a[1]), "r"(a[2]), "r"(a[3]), "r"(b[0]), "r"(b[1]));
}
__device__ __forceinline__ void st4tf(float* p, float4 v) {
    *(float4*)p = make_float4(tf32r(v.x), tf32r(v.y), tf32r(v.z), tf32r(v.w));
}
__device__ __forceinline__ unsigned long long fma2(unsigned long long a,
                                                   unsigned long long b,
                                                   unsigned long long c) {
    unsigned long long d;
    asm("fma.rn.f32x2 %0, %1, %2, %3;" : "=l"(d) : "l"(a), "l"(b), "l"(c));
    return d;
}
__device__ __forceinline__ unsigned long long pk(float a, float b) {
    unsigned long long v;
    asm("mov.b64 %0, {%1,%2};" : "=l"(v) : "f"(a), "f"(b));
    return v;
}
__device__ __forceinline__ float2 unpk(unsigned long long v) {
    float2 r;
    asm("mov.b64 {%0,%1}, %2;" : "=f"(r.x), "=f"(r.y) : "l"(v));
    return r;
}
// Cody-Waite reduction + MUFU sin/cos (|x| <= ~800, n <= ~128 -> residual ~1e-8)
__device__ __forceinline__ void fast_sincos(float x, float* s, float* c) {
    float n = rintf(x * 0.15915494309189535f);
    float r = fmaf(n, -6.28125f, x);
    r = fmaf(n, -1.9353071795864769e-3f, r);
    *s = __sinf(r);
    *c = __cosf(r);
}

// ---------------- box param prep ----------------
__global__ void prep_boxes_kernel(const float* __restrict__ bbox,
                                  const float* __restrict__ refb)
{
    int i = blockIdx.x * 256 + threadIdx.x;
    if (i < NN) {
        float x0 = bbox[i*4+0], y0 = bbox[i*4+1], x1 = bbox[i*4+2], y1 = bbox[i*4+3];
        d_roip[i] = make_float4(0.5f*(x0+x1), 0.5f*(y0+y1), x1 - x0 + 1.0f, y1 - y0 + 1.0f);
    }
    if (i < MM) {
        float x0 = refb[i*4+0], y0 = refb[i*4+1], x1 = refb[i*4+2], y1 = refb[i*4+3];
        d_refp[i] = make_float4(0.5f*(x0+x1), 0.5f*(y0+y1), x1 - x0 + 1.0f, y1 - y0 + 1.0f);
    }
}

// ---------------- position prior:  logw[g][n][m] ----------------
__global__ __launch_bounds__(128)
void logw_kernel(const float* __restrict__ Wg_w, const float* __restrict__ Wg_b)
{
    __shared__ __align__(16) float wg[GG * 64];
    __shared__ float wgb[GG];
    int n = blockIdx.y;
    int m = blockIdx.x * 128 + threadIdx.x;
    for (int t = threadIdx.x; t < GG * 64; t += 128) wg[t] = Wg_w[t];
    if (threadIdx.x < GG) wgb[threadIdx.x] = Wg_b[threadIdx.x];
    float4 rp = d_roip[n];
    float4 fp = d_refp[m];
    __syncthreads();

    float pos[4];
    pos[0] = logf(fabsf((rp.x - fp.x) / rp.z) + 1e-3f);
    pos[1] = logf(fabsf((rp.y - fp.y) / rp.w) + 1e-3f);
    pos[2] = logf(rp.z / fp.z);
    pos[3] = logf(rp.w / fp.w);

    // rdm[f] = 1000^(-f/8) (correctly-rounded fp32)
    const float rdm[8] = {1.0f, 0.42169650f, 0.17782794f, 0.074989421f,
                          0.031622777f, 0.013335214f, 0.0056234133f, 0.0023713737f};
    // packed emb pairs: e2[j] = (emb[2j], emb[2j+1])
    unsigned long long e2[32];
#pragma unroll
    for (int i = 0; i < 4; i++) {
        float p100 = pos[i] * 100.0f;
#pragma unroll
        for (int f = 0; f < 8; f += 2) {
            float s0, c0, s1, c1;
            fast_sincos(p100 * rdm[f],     &s0, &c0);
            fast_sincos(p100 * rdm[f + 1], &s1, &c1);
            e2[i*8 +     (f >> 1)] = pk(s0, s1);
            e2[i*8 + 4 + (f >> 1)] = pk(c0, c1);
        }
    }

    const unsigned long long* wg64 = (const unsigned long long*)wg;
    size_t base = (size_t)n * MM + m;
#pragma unroll 1
    for (int g = 0; g < GG; g++) {
        unsigned long long a0 = 0ull, a1 = 0ull;
#pragma unroll
        for (int j = 0; j < 32; j += 2) {
            a0 = fma2(wg64[g*32 + j],     e2[j],     a0);
            a1 = fma2(wg64[g*32 + j + 1], e2[j + 1], a1);
        }
        float2 f0 = unpk(a0), f1 = unpk(a1);
        float a = wgb[g] + ((f0.x + f0.y) + (f1.x + f1.y));
        a = fmaxf(a, 0.0f) + 1e-6f;
        d_logw[(size_t)g * NN * MM + base] = __logf(a);
    }
}

// ---------------- mega tf32 NT GEMM: q,k,v in one launch ----------------
// by 0..15 : A=ref_feat (2048 rows); bx 0..7 -> k (bias Wk_b), bx 8..15 -> v
// by 16..19: A=roi_feat (512 rows);  bx 0..7 -> q (bias Wq_b + u, scale 1/8)
__global__ __launch_bounds__(256, 2)
void megagemm(const float* __restrict__ roi, const float* __restrict__ ref,
              const float* __restrict__ Wq, const float* __restrict__ Wq_b,
              const float* __restrict__ Wk, const float* __restrict__ Wk_b,
              const float* __restrict__ Wv, const float* __restrict__ u)
{
    __shared__ __align__(16) float As[2][128][20];
    __shared__ __align__(16) float Bs[2][128][20];
    const int K = 1024;
    int bx = blockIdx.x, by = blockIdx.y;
    int bo = bx * 128;
    const float *A, *B, *bias = nullptr, *bias2 = nullptr;
    float scale = 1.0f; float* C; int cb, br;
    if (by < 16) {
        br = by * 128; A = ref;
        if (bo < 1024) { B = Wk + (size_t)bo * K; bias = Wk_b + bo; C = d_k; cb = bo; }
        else           { B = Wv + (size_t)(bo - 1024) * K; C = d_v; cb = bo - 1024; }
    } else {
        if (bx >= 8) return;
        br = (by - 16) * 128; A = roi;
        B = Wq + (size_t)bo * K; bias = Wq_b + bo; bias2 = u + bo;
        C = d_q; cb = bo; scale = 0.125f;
    }

    int tid = threadIdx.x, wid = tid >> 5, lane = tid & 31;
    int gr = lane >> 2, t = lane & 3;
    int wm = (wid >> 2) * 64, wn = (wid & 3) * 32;
    int lr = tid >> 2, lc = (tid & 3) * 4;
    const float* Ap = A + (size_t)(br + lr) * K + lc;
    const float* Bp = B + (size_t)lr * K + lc;

    float c[4][4][4];
#pragma unroll
    for (int i = 0; i < 4; i++)
#pragma unroll
        for (int j = 0; j < 4; j++)
#pragma unroll
            for (int q = 0; q < 4; q++) c[i][j][q] = 0.0f;

    float4 pa0 = *(const float4*)(Ap);
    float4 pa1 = *(const float4*)(Ap + 64 * K);
    float4 pb0 = *(const float4*)(Bp);
    float4 pb1 = *(const float4*)(Bp + 64 * K);
    st4tf(&As[0][lr][lc], pa0); st4tf(&As[0][lr + 64][lc], pa1);
    st4tf(&Bs[0][lr][lc], pb0); st4tf(&Bs[0][lr + 64][lc], pb1);
    __syncthreads();

    for (int k0 = 0; k0 < K; k0 += 16) {
        int buf = (k0 >> 4) & 1;
        bool more = (k0 + 16) < K;
        if (more) {
            pa0 = *(const float4*)(Ap + k0 + 16);
            pa1 = *(const float4*)(Ap + 64 * K + k0 + 16);
            pb0 = *(const float4*)(Bp + k0 + 16);
            pb1 = *(const float4*)(Bp + 64 * K + k0 + 16);
        }
#pragma unroll
        for (int ks = 0; ks < 16; ks += 8) {
            uint32_t a[4][4], b[4][2];
#pragma unroll
            for (int mt = 0; mt < 4; mt++) {
                a[mt][0] = __float_as_uint(As[buf][wm + mt*16 + gr    ][ks + t    ]);
                a[mt][1] = __float_as_uint(As[buf][wm + mt*16 + gr + 8][ks + t    ]);
                a[mt][2] = __float_as_uint(As[buf][wm + mt*16 + gr    ][ks + t + 4]);
                a[mt][3] = __float_as_uint(As[buf][wm + mt*16 + gr + 8][ks + t + 4]);
            }
#pragma unroll
            for (int nt = 0; nt < 4; nt++) {
                b[nt][0] = __float_as_uint(Bs[buf][wn + nt*8 + gr][ks + t    ]);
                b[nt][1] = __float_as_uint(Bs[buf][wn + nt*8 + gr][ks + t + 4]);
            }
#pragma unroll
            for (int mt = 0; mt < 4; mt++)
#pragma unroll
                for (int nt = 0; nt < 4; nt++) mma8(c[mt][nt], a[mt], b[nt]);
        }
        if (more) {
            int nb = buf ^ 1;
            st4tf(&As[nb][lr][lc], pa0); st4tf(&As[nb][lr + 64][lc], pa1);
            st4tf(&Bs[nb][lr][lc], pb0); st4tf(&Bs[nb][lr + 64][lc], pb1);
        }
        __syncthreads();
    }

#pragma unroll
    for (int mt = 0; mt < 4; mt++) {
        int r0 = br + wm + mt*16 + gr;
#pragma unroll
        for (int nt = 0; nt < 4; nt++) {
            int lo = wn + nt*8 + 2*t;
            float v0 = c[mt][nt][0], v1 = c[mt][nt][1];
            float v2 = c[mt][nt][2], v3 = c[mt][nt][3];
            if (bias)  { float b0 = bias[lo],  b1 = bias[lo+1];  v0 += b0; v2 += b0; v1 += b1; v3 += b1; }
            if (bias2) { float b0 = bias2[lo], b1 = bias2[lo+1]; v0 += b0; v2 += b0; v1 += b1; v3 += b1; }
            *(float2*)&C[(size_t)r0 * FEAT + cb + lo] =
                make_float2(tf32r(v0 * scale), tf32r(v1 * scale));
            *(float2*)&C[(size_t)(r0 + 8) * FEAT + cb + lo] =
                make_float2(tf32r(v2 * scale), tf32r(v3 * scale));
        }
    }
}

// ---------------- split-KV flash attention (partials) ----------------
#define ST 68
#define SV 72
// grid (NN/64, GG, NSPLIT), 128 threads. Warp owns 16 rows end-to-end.
__global__ __launch_bounds__(128, 3)
void attn_split_kernel()
{
    extern __shared__ __align__(16) float sm[];
    float* Ks = sm;                 // [64][68]
    float* Vs = Ks + 64 * ST;       // [64][72]
    float* Ps = Vs + 64 * SV;       // [64][68]
    float* Ls = Ps + 64 * ST;       // [64][68]

    int g = blockIdx.y, n0 = blockIdx.x * 64, sp = blockIdx.z;
    int mbase = sp * (MM / NSPLIT);
    int tid = threadIdx.x, wid = tid >> 5, lane = tid & 31;
    int gr = lane >> 2, t = lane & 3;
    int row0 = wid * 16 + gr, row1 = row0 + 8;

    // Q fragments: loop-invariant, live in registers (values pre-rounded to tf32)
    uint32_t qf[8][4];
#pragma unroll
    for (int ks8 = 0; ks8 < 8; ks8++) {
        const float* qb = d_q + (size_t)n0 * FEAT + g * 64 + ks8 * 8;
        qf[ks8][0] = __float_as_uint(qb[(size_t)row0 * FEAT + t    ]);
        qf[ks8][1] = __float_as_uint(qb[(size_t)row1 * FEAT + t    ]);
        qf[ks8][2] = __float_as_uint(qb[(size_t)row0 * FEAT + t + 4]);
        qf[ks8][3] = __float_as_uint(qb[(size_t)row1 * FEAT + t + 4]);
    }

    float accO[8][4];
#pragma unroll
    for (int i = 0; i < 8; i++)
#pragma unroll
        for (int j = 0; j < 4; j++) accO[i][j] = 0.0f;
    float rmax0 = -1e30f, rmax1 = -1e30f, rsum0 = 0.0f, rsum1 = 0.0f;

    for (int mi = 0; mi < MM / NSPLIT; mi += 64) {
        int m0 = mbase + mi;
        for (int idx = tid; idx < 64 * 16; idx += 128) {
            int r = idx >> 4, c4 = (idx & 15) * 4;
            *(float4*)&Ks[r*ST + c4] = *(const float4*)&d_k[(size_t)(m0 + r) * FEAT + g*64 + c4];
            *(float4*)&Vs[r*SV + c4] = *(const float4*)&d_v[(size_t)(m0 + r) * FEAT + g*64 + c4];
            *(float4*)&Ls[r*ST + c4] =
                *(const float4*)&d_logw[((size_t)g * NN + (n0 + r)) * MM + m0 + c4];
        }
        __syncthreads();

        float s[8][4];
#pragma unroll
        for (int i = 0; i < 8; i++)
#pragma unroll
            for (int j = 0; j < 4; j++) s[i][j] = 0.0f;
#pragma unroll
        for (int ks = 0; ks < 8; ks++) {
#pragma unroll
            for (int nt = 0; nt < 8; nt++) {
                uint32_t b[2];
                b[0] = __float_as_uint(Ks[(nt*8 + gr)*ST + ks*8 + t    ]);
                b[1] = __float_as_uint(Ks[(nt*8 + gr)*ST + ks*8 + t + 4]);
                mma8(s[nt], qf[ks], b);
            }
        }
#pragma unroll
        for (int nt = 0; nt < 8; nt++) {
            int c0 = nt*8 + 2*t;
            float2 l0 = *(const float2*)&Ls[row0*ST + c0];
            float2 l1 = *(const float2*)&Ls[row1*ST + c0];
            s[nt][0] += l0.x; s[nt][1] += l0.y;
            s[nt][2] += l1.x; s[nt][3] += l1.y;
        }
        float m0v = rmax0, m1v = rmax1;
#pragma unroll
        for (int nt = 0; nt < 8; nt++) {
            m0v = fmaxf(m0v, fmaxf(s[nt][0], s[nt][1]));
            m1v = fmaxf(m1v, fmaxf(s[nt][2], s[nt][3]));
        }
        m0v = fmaxf(m0v, __shfl_xor_sync(0xffffffffu, m0v, 1));
        m0v = fmaxf(m0v, __shfl_xor_sync(0xffffffffu, m0v, 2));
        m1v = fmaxf(m1v, __shfl_xor_sync(0xffffffffu, m1v, 1));
        m1v = fmaxf(m1v, __shfl_xor_sync(0xffffffffu, m1v, 2));
        float fac0 = __expf(rmax0 - m0v), fac1 = __expf(rmax1 - m1v);
        rmax0 = m0v; rmax1 = m1v;
        float sum0 = 0.0f, sum1 = 0.0f;
#pragma unroll
        for (int nt = 0; nt < 8; nt++) {
            int c0 = nt*8 + 2*t;
            float p0 = __expf(s[nt][0] - m0v);
            float p1 = __expf(s[nt][1] - m0v);
            float p2 = __expf(s[nt][2] - m1v);
            float p3 = __expf(s[nt][3] - m1v);
            sum0 += p0 + p1; sum1 += p2 + p3;
            *(float2*)&Ps[row0*ST + c0] = make_float2(tf32r(p0), tf32r(p1));
            *(float2*)&Ps[row1*ST + c0] = make_float2(tf32r(p2), tf32r(p3));
        }
        sum0 += __shfl_xor_sync(0xffffffffu, sum0, 1);
        sum0 += __shfl_xor_sync(0xffffffffu, sum0, 2);
        sum1 += __shfl_xor_sync(0xffffffffu, sum1, 1);
        sum1 += __shfl_xor_sync(0xffffffffu, sum1, 2);
        rsum0 = rsum0 * fac0 + sum0;
        rsum1 = rsum1 * fac1 + sum1;
#pragma unroll
        for (int dt = 0; dt < 8; dt++) {
            accO[dt][0] *= fac0; accO[dt][1] *= fac0;
            accO[dt][2] *= fac1; accO[dt][3] *= fac1;
        }
        __syncwarp();

#pragma unroll
        for (int ks = 0; ks < 8; ks++) {
            uint32_t a[4];
            a[0] = __float_as_uint(Ps[row0*ST + ks*8 + t    ]);
            a[1] = __float_as_uint(Ps[row1*ST + ks*8 + t    ]);
            a[2] = __float_as_uint(Ps[row0*ST + ks*8 + t + 4]);
            a[3] = __float_as_uint(Ps[row1*ST + ks*8 + t + 4]);
#pragma unroll
            for (int dt = 0; dt < 8; dt++) {
                uint32_t b[2];
                b[0] = __float_as_uint(Vs[(ks*8 + t    )*SV + dt*8 + gr]);
                b[1] = __float_as_uint(Vs[(ks*8 + t + 4)*SV + dt*8 + gr]);
                mma8(accO[dt], a, b);
            }
        }
        __syncthreads();
    }

    // write unnormalized partials + stats
    if (t == 0) {
        d_pstat[((size_t)sp * GG + g) * NN + n0 + row0] = make_float2(rmax0, rsum0);
        d_pstat[((size_t)sp * GG + g) * NN + n0 + row1] = make_float2(rmax1, rsum1);
    }
    float* po = d_po + (size_t)sp * NN * FEAT;
#pragma unroll
    for (int dt = 0; dt < 8; dt++) {
        int o = g*64 + dt*8 + 2*t;
        *(float2*)&po[(size_t)(n0 + row0) * FEAT + o] = make_float2(accO[dt][0], accO[dt][1]);
        *(float2*)&po[(size_t)(n0 + row1) * FEAT + o] = make_float2(accO[dt][2], accO[dt][3]);
    }
}

// ---------------- merge partials -> final output ----------------
__global__ __launch_bounds__(256)
void merge_kernel(const float* __restrict__ Wv_b, float* __restrict__ out)
{
    int idx = blockIdx.x * 256 + threadIdx.x;
    int n = idx >> 10, o = idx & 1023, g = o >> 6;
    float2 st[NSPLIT];
    float M = -1e30f;
#pragma unroll
    for (int s = 0; s < NSPLIT; s++) {
        st[s] = d_pstat[((size_t)s * GG + g) * NN + n];
        M = fmaxf(M, st[s].x);
    }
    float num = 0.0f, den = 0.0f;
#pragma unroll
    for (int s = 0; s < NSPLIT; s++) {
        float w = __expf(st[s].x - M);
        num += d_po[((size_t)s * NN + n) * FEAT + o] * w;
        den += st[s].y * w;
    }
    out[idx] = num / den + Wv_b[o];
}

// ---------------- launch ----------------
extern "C" void kernel_launch(void* const* d_in, const int* in_sizes, int n_in,
                              void* d_out, int out_size)
{
    const float* bbox     = (const float*)d_in[0];
    const float* ref_bbox = (const float*)d_in[1];
    const float* roi_feat = (const float*)d_in[2];
    const float* ref_feat = (const float*)d_in[3];
    const float* Wg_w     = (const float*)d_in[4];
    const float* Wg_b     = (const float*)d_in[5];
    const float* Wq_w     = (const float*)d_in[6];
    const float* Wq_b     = (const float*)d_in[7];
    const float* Wk_w     = (const float*)d_in[8];
    const float* Wk_b     = (const float*)d_in[9];
    const float* Wv_w     = (const float*)d_in[10];
    const float* Wv_b     = (const float*)d_in[11];
    const float* u        = (const float*)d_in[12];
    float* out = (float*)d_out;

    (void)in_sizes; (void)n_in; (void)out_size;

    static const int ATTN_SMEM = (64 * ST * 3 + 64 * SV) * 4;   // 70656 B
    cudaFuncSetAttribute(attn_split_kernel, cudaFuncAttributeMaxDynamicSharedMemorySize, ATTN_SMEM);

    prep_boxes_kernel<<<8, 256>>>(bbox, ref_bbox);
    logw_kernel<<<dim3(MM / 128, NN), 128>>>(Wg_w, Wg_b);
    megagemm<<<dim3(16, 20), 256>>>(roi_feat, ref_feat, Wq_w, Wq_b,
                                    Wk_w, Wk_b, Wv_w, u);
    attn_split_kernel<<<dim3(NN / 64, GG, NSPLIT), 128, ATTN_SMEM>>>();
    merge_kernel<<<NN * FEAT / 256, 256>>>(Wv_b, out);
}

// round 6
// speedup vs baseline: 4.2199x; 1.0769x over previous
#include <cuda_runtime.h>
#include <math.h>
#include <stdint.h>

#define NN 512
#define MM 2048
#define FEAT 1024
#define GG 16
#define DG 64
#define NSPLIT 4

// ---------------- scratch (device globals; no allocation) ----------------
__device__ float d_q[NN * FEAT];                      // (q + u)/8, tf32-rounded
__device__ float d_k[MM * FEAT];                      // k, tf32-rounded
__device__ float d_v[MM * FEAT];                      // V = ref_feat @ Wv^T, tf32-rounded
__device__ float d_w[(size_t)GG * NN * MM];           // relu(Wg.pe)+1e-6  (NOT log)
__device__ float4 d_roip[NN];
__device__ float4 d_refp[MM];
__device__ float  d_po[(size_t)NSPLIT * NN * FEAT];   // unnormalized partial O
__device__ float2 d_pstat[NSPLIT * GG * NN];          // (running max of s, running sum)

// ---------------- helpers ----------------
__device__ __forceinline__ float tf32r(float x) {
    uint32_t u;
    asm("cvt.rna.tf32.f32 %0, %1;" : "=r"(u) : "f"(x));
    return __uint_as_float(u);
}
__device__ __forceinline__ void mma8(float* c, const uint32_t* a, const uint32_t* b) {
    asm volatile(
        "mma.sync.aligned.m16n8k8.row.col.f32.tf32.tf32.f32 "
        "{%0,%1,%2,%3}, {%4,%5,%6,%7}, {%8,%9}, {%0,%1,%2,%3};"
        : "+f"(c[0]), "+f"(c[1]), "+f"(c[2]), "+f"(c[3])
        : "r"(a[0]), "r"(a[1]), "r"(a[2]), "r"(a[3]), "r"(b[0]), "r"(b[1]));
}
__device__ __forceinline__ void st4tf(float* p, float4 v) {
    *(float4*)p = make_float4(tf32r(v.x), tf32r(v.y), tf32r(v.z), tf32r(v.w));
}
__device__ __forceinline__ unsigned long long fma2(unsigned long long a,
                                                   unsigned long long b,
                                                   unsigned long long c) {
    unsigned long long d;
    asm("fma.rn.f32x2 %0, %1, %2, %3;" : "=l"(d) : "l"(a), "l"(b), "l"(c));
    return d;
}
__device__ __forceinline__ unsigned long long pk(float a, float b) {
    unsigned long long v;
    asm("mov.b64 %0, {%1,%2};" : "=l"(v) : "f"(a), "f"(b));
    return v;
}
__device__ __forceinline__ float2 unpk(unsigned long long v) {
    float2 r;
    asm("mov.b64 {%0,%1}, %2;" : "=f"(r.x), "=f"(r.y) : "l"(v));
    return r;
}
__device__ __forceinline__ void fast_sincos(float x, float* s, float* c) {
    float n = rintf(x * 0.15915494309189535f);
    float r = fmaf(n, -6.28125f, x);
    r = fmaf(n, -1.9353071795864769e-3f, r);
    *s = __sinf(r);
    *c = __cosf(r);
}
__device__ __forceinline__ void cpa16(void* s, const void* g) {
    uint32_t sa = (uint32_t)__cvta_generic_to_shared(s);
    asm volatile("cp.async.ca.shared.global [%0], [%1], 16;" :: "r"(sa), "l"(g));
}
#define CP_COMMIT() asm volatile("cp.async.commit_group;" ::: "memory")
#define CP_WAIT(n)  asm volatile("cp.async.wait_group %0;" :: "n"(n) : "memory")

// ---------------- box param prep ----------------
__global__ void prep_boxes_kernel(const float* __restrict__ bbox,
                                  const float* __restrict__ refb)
{
    int i = blockIdx.x * 256 + threadIdx.x;
    if (i < NN) {
        float x0 = bbox[i*4+0], y0 = bbox[i*4+1], x1 = bbox[i*4+2], y1 = bbox[i*4+3];
        d_roip[i] = make_float4(0.5f*(x0+x1), 0.5f*(y0+y1), x1 - x0 + 1.0f, y1 - y0 + 1.0f);
    }
    if (i < MM) {
        float x0 = refb[i*4+0], y0 = refb[i*4+1], x1 = refb[i*4+2], y1 = refb[i*4+3];
        d_refp[i] = make_float4(0.5f*(x0+x1), 0.5f*(y0+y1), x1 - x0 + 1.0f, y1 - y0 + 1.0f);
    }
}

// ---------------- position prior:  w[g][n][m] = relu(Wg.pe)+1e-6 ----------------
__global__ __launch_bounds__(128)
void w_kernel(const float* __restrict__ Wg_w, const float* __restrict__ Wg_b)
{
    __shared__ __align__(16) float wg[GG * 64];
    __shared__ float wgb[GG];
    int n = blockIdx.y;
    int m = blockIdx.x * 128 + threadIdx.x;
    for (int t = threadIdx.x; t < GG * 64; t += 128) wg[t] = Wg_w[t];
    if (threadIdx.x < GG) wgb[threadIdx.x] = Wg_b[threadIdx.x];
    float4 rp = d_roip[n];
    float4 fp = d_refp[m];
    __syncthreads();

    float pos[4];
    pos[0] = logf(fabsf((rp.x - fp.x) / rp.z) + 1e-3f);
    pos[1] = logf(fabsf((rp.y - fp.y) / rp.w) + 1e-3f);
    pos[2] = logf(rp.z / fp.z);
    pos[3] = logf(rp.w / fp.w);

    const float rdm[8] = {1.0f, 0.42169650f, 0.17782794f, 0.074989421f,
                          0.031622777f, 0.013335214f, 0.0056234133f, 0.0023713737f};
    unsigned long long e2[32];
#pragma unroll
    for (int i = 0; i < 4; i++) {
        float p100 = pos[i] * 100.0f;
#pragma unroll
        for (int f = 0; f < 8; f += 2) {
            float s0, c0, s1, c1;
            fast_sincos(p100 * rdm[f],     &s0, &c0);
            fast_sincos(p100 * rdm[f + 1], &s1, &c1);
            e2[i*8 +     (f >> 1)] = pk(s0, s1);
            e2[i*8 + 4 + (f >> 1)] = pk(c0, c1);
        }
    }

    const unsigned long long* wg64 = (const unsigned long long*)wg;
    size_t base = (size_t)n * MM + m;
#pragma unroll 1
    for (int g = 0; g < GG; g++) {
        unsigned long long a0 = 0ull, a1 = 0ull;
#pragma unroll
        for (int j = 0; j < 32; j += 2) {
            a0 = fma2(wg64[g*32 + j],     e2[j],     a0);
            a1 = fma2(wg64[g*32 + j + 1], e2[j + 1], a1);
        }
        float2 f0 = unpk(a0), f1 = unpk(a1);
        float a = wgb[g] + ((f0.x + f0.y) + (f1.x + f1.y));
        d_w[(size_t)g * NN * MM + base] = fmaxf(a, 0.0f) + 1e-6f;
    }
}

// ---------------- mega tf32 NT GEMM: q,k,v in one launch ----------------
__global__ __launch_bounds__(256, 2)
void megagemm(const float* __restrict__ roi, const float* __restrict__ ref,
              const float* __restrict__ Wq, const float* __restrict__ Wq_b,
              const float* __restrict__ Wk, const float* __restrict__ Wk_b,
              const float* __restrict__ Wv, const float* __restrict__ u)
{
    __shared__ __align__(16) float As[2][128][20];
    __shared__ __align__(16) float Bs[2][128][20];
    const int K = 1024;
    int bx = blockIdx.x, by = blockIdx.y;
    int bo = bx * 128;
    const float *A, *B, *bias = nullptr, *bias2 = nullptr;
    float scale = 1.0f; float* C; int cb, br;
    if (by < 16) {
        br = by * 128; A = ref;
        if (bo < 1024) { B = Wk + (size_t)bo * K; bias = Wk_b + bo; C = d_k; cb = bo; }
        else           { B = Wv + (size_t)(bo - 1024) * K; C = d_v; cb = bo - 1024; }
    } else {
        if (bx >= 8) return;
        br = (by - 16) * 128; A = roi;
        B = Wq + (size_t)bo * K; bias = Wq_b + bo; bias2 = u + bo;
        C = d_q; cb = bo; scale = 0.125f;
    }

    int tid = threadIdx.x, wid = tid >> 5, lane = tid & 31;
    int gr = lane >> 2, t = lane & 3;
    int wm = (wid >> 2) * 64, wn = (wid & 3) * 32;
    int lr = tid >> 2, lc = (tid & 3) * 4;
    const float* Ap = A + (size_t)(br + lr) * K + lc;
    const float* Bp = B + (size_t)lr * K + lc;

    float c[4][4][4];
#pragma unroll
    for (int i = 0; i < 4; i++)
#pragma unroll
        for (int j = 0; j < 4; j++)
#pragma unroll
            for (int q = 0; q < 4; q++) c[i][j][q] = 0.0f;

    float4 pa0 = *(const float4*)(Ap);
    float4 pa1 = *(const float4*)(Ap + 64 * K);
    float4 pb0 = *(const float4*)(Bp);
    float4 pb1 = *(const float4*)(Bp + 64 * K);
    st4tf(&As[0][lr][lc], pa0); st4tf(&As[0][lr + 64][lc], pa1);
    st4tf(&Bs[0][lr][lc], pb0); st4tf(&Bs[0][lr + 64][lc], pb1);
    __syncthreads();

    for (int k0 = 0; k0 < K; k0 += 16) {
        int buf = (k0 >> 4) & 1;
        bool more = (k0 + 16) < K;
        if (more) {
            pa0 = *(const float4*)(Ap + k0 + 16);
            pa1 = *(const float4*)(Ap + 64 * K + k0 + 16);
            pb0 = *(const float4*)(Bp + k0 + 16);
            pb1 = *(const float4*)(Bp + 64 * K + k0 + 16);
        }
#pragma unroll
        for (int ks = 0; ks < 16; ks += 8) {
            uint32_t a[4][4], b[4][2];
#pragma unroll
            for (int mt = 0; mt < 4; mt++) {
                a[mt][0] = __float_as_uint(As[buf][wm + mt*16 + gr    ][ks + t    ]);
                a[mt][1] = __float_as_uint(As[buf][wm + mt*16 + gr + 8][ks + t    ]);
                a[mt][2] = __float_as_uint(As[buf][wm + mt*16 + gr    ][ks + t + 4]);
                a[mt][3] = __float_as_uint(As[buf][wm + mt*16 + gr + 8][ks + t + 4]);
            }
#pragma unroll
            for (int nt = 0; nt < 4; nt++) {
                b[nt][0] = __float_as_uint(Bs[buf][wn + nt*8 + gr][ks + t    ]);
                b[nt][1] = __float_as_uint(Bs[buf][wn + nt*8 + gr][ks + t + 4]);
            }
#pragma unroll
            for (int mt = 0; mt < 4; mt++)
#pragma unroll
                for (int nt = 0; nt < 4; nt++) mma8(c[mt][nt], a[mt], b[nt]);
        }
        if (more) {
            int nb = buf ^ 1;
            st4tf(&As[nb][lr][lc], pa0); st4tf(&As[nb][lr + 64][lc], pa1);
            st4tf(&Bs[nb][lr][lc], pb0); st4tf(&Bs[nb][lr + 64][lc], pb1);
        }
        __syncthreads();
    }

#pragma unroll
    for (int mt = 0; mt < 4; mt++) {
        int r0 = br + wm + mt*16 + gr;
#pragma unroll
        for (int nt = 0; nt < 4; nt++) {
            int lo = wn + nt*8 + 2*t;
            float v0 = c[mt][nt][0], v1 = c[mt][nt][1];
            float v2 = c[mt][nt][2], v3 = c[mt][nt][3];
            if (bias)  { float b0 = bias[lo],  b1 = bias[lo+1];  v0 += b0; v2 += b0; v1 += b1; v3 += b1; }
            if (bias2) { float b0 = bias2[lo], b1 = bias2[lo+1]; v0 += b0; v2 += b0; v1 += b1; v3 += b1; }
            *(float2*)&C[(size_t)r0 * FEAT + cb + lo] =
                make_float2(tf32r(v0 * scale), tf32r(v1 * scale));
            *(float2*)&C[(size_t)(r0 + 8) * FEAT + cb + lo] =
                make_float2(tf32r(v2 * scale), tf32r(v3 * scale));
        }
    }
}

// ---------------- split-KV flash attention (partials) ----------------
#define ST 68   // K stride (floats); 272B, 16B-aligned rows, conflict-free frags
#define SV 72   // V stride; 288B
#define BUFSZ (64 * ST + 64 * SV)   // floats per pipeline stage
// grid (NN/64, GG, NSPLIT), 128 threads. Warp owns 16 rows end-to-end.
__global__ __launch_bounds__(128, 3)
void attn_split_kernel()
{
    extern __shared__ __align__(16) float sm[];

    int g = blockIdx.y, n0 = blockIdx.x * 64, sp = blockIdx.z;
    int mbase = sp * (MM / NSPLIT);
    int tid = threadIdx.x, wid = tid >> 5, lane = tid & 31;
    int gr = lane >> 2, t = lane & 3;
    int row0 = wid * 16 + gr, row1 = row0 + 8;

    // Q fragments: loop-invariant registers (values tf32-rounded at source)
    uint32_t qf[8][4];
#pragma unroll
    for (int ks8 = 0; ks8 < 8; ks8++) {
        const float* qb = d_q + (size_t)n0 * FEAT + g * 64 + ks8 * 8;
        qf[ks8][0] = __float_as_uint(qb[(size_t)row0 * FEAT + t    ]);
        qf[ks8][1] = __float_as_uint(qb[(size_t)row1 * FEAT + t    ]);
        qf[ks8][2] = __float_as_uint(qb[(size_t)row0 * FEAT + t + 4]);
        qf[ks8][3] = __float_as_uint(qb[(size_t)row1 * FEAT + t + 4]);
    }

    float accO[8][4];
#pragma unroll
    for (int i = 0; i < 8; i++)
#pragma unroll
        for (int j = 0; j < 4; j++) accO[i][j] = 0.0f;
    float rmax0 = -1e30f, rmax1 = -1e30f, rsum0 = 0.0f, rsum1 = 0.0f;

    const float* wbase = d_w + ((size_t)g * NN + n0) * MM + mbase;
    const int NT = (MM / NSPLIT) / 64;   // 8 tiles

    // prefetch tile 0
    {
        float* Kb = sm; float* Vb = sm + 64 * ST;
        for (int idx = tid; idx < 1024; idx += 128) {
            int r = idx >> 4, c4 = (idx & 15) * 4;
            cpa16(&Kb[r*ST + c4], &d_k[(size_t)(mbase + r) * FEAT + g*64 + c4]);
            cpa16(&Vb[r*SV + c4], &d_v[(size_t)(mbase + r) * FEAT + g*64 + c4]);
        }
        CP_COMMIT();
    }

    for (int it = 0; it < NT; it++) {
        int buf = it & 1;
        float* Kb = sm + buf * BUFSZ;
        float* Vb = Kb + 64 * ST;
        if (it + 1 < NT) {
            float* Kn = sm + (buf ^ 1) * BUFSZ;
            float* Vn = Kn + 64 * ST;
            int m0 = mbase + (it + 1) * 64;
            for (int idx = tid; idx < 1024; idx += 128) {
                int r = idx >> 4, c4 = (idx & 15) * 4;
                cpa16(&Kn[r*ST + c4], &d_k[(size_t)(m0 + r) * FEAT + g*64 + c4]);
                cpa16(&Vn[r*SV + c4], &d_v[(size_t)(m0 + r) * FEAT + g*64 + c4]);
            }
            CP_COMMIT();
            CP_WAIT(1);
        } else {
            CP_WAIT(0);
        }
        __syncthreads();

        // S = Q K^T  (warp tile 16x64)
        float s[8][4];
#pragma unroll
        for (int i = 0; i < 8; i++)
#pragma unroll
            for (int j = 0; j < 4; j++) s[i][j] = 0.0f;
#pragma unroll
        for (int ks = 0; ks < 8; ks++) {
#pragma unroll
            for (int nt = 0; nt < 8; nt++) {
                uint32_t b[2];
                b[0] = __float_as_uint(Kb[(nt*8 + gr)*ST + ks*8 + t    ]);
                b[1] = __float_as_uint(Kb[(nt*8 + gr)*ST + ks*8 + t + 4]);
                mma8(s[nt], qf[ks], b);
            }
        }

        // prior weights (registers, global loads covered by reduction below)
        const float* wt = wbase + it * 64;
        float2 w0[8], w1[8];
#pragma unroll
        for (int nt = 0; nt < 8; nt++) {
            w0[nt] = *(const float2*)&wt[(size_t)row0 * MM + nt*8 + 2*t];
            w1[nt] = *(const float2*)&wt[(size_t)row1 * MM + nt*8 + 2*t];
        }

        // online softmax over s only (prior applied multiplicatively)
        float m0v = rmax0, m1v = rmax1;
#pragma unroll
        for (int nt = 0; nt < 8; nt++) {
            m0v = fmaxf(m0v, fmaxf(s[nt][0], s[nt][1]));
            m1v = fmaxf(m1v, fmaxf(s[nt][2], s[nt][3]));
        }
        m0v = fmaxf(m0v, __shfl_xor_sync(0xffffffffu, m0v, 1));
        m0v = fmaxf(m0v, __shfl_xor_sync(0xffffffffu, m0v, 2));
        m1v = fmaxf(m1v, __shfl_xor_sync(0xffffffffu, m1v, 1));
        m1v = fmaxf(m1v, __shfl_xor_sync(0xffffffffu, m1v, 2));
        float fac0 = __expf(rmax0 - m0v), fac1 = __expf(rmax1 - m1v);
        rmax0 = m0v; rmax1 = m1v;
        float sum0 = 0.0f, sum1 = 0.0f;
#pragma unroll
        for (int nt = 0; nt < 8; nt++) {
            float p0 = w0[nt].x * __expf(s[nt][0] - m0v);
            float p1 = w0[nt].y * __expf(s[nt][1] - m0v);
            float p2 = w1[nt].x * __expf(s[nt][2] - m1v);
            float p3 = w1[nt].y * __expf(s[nt][3] - m1v);
            sum0 += p0 + p1; sum1 += p2 + p3;
            s[nt][0] = tf32r(p0); s[nt][1] = tf32r(p1);
            s[nt][2] = tf32r(p2); s[nt][3] = tf32r(p3);
        }
        sum0 += __shfl_xor_sync(0xffffffffu, sum0, 1);
        sum0 += __shfl_xor_sync(0xffffffffu, sum0, 2);
        sum1 += __shfl_xor_sync(0xffffffffu, sum1, 1);
        sum1 += __shfl_xor_sync(0xffffffffu, sum1, 2);
        rsum0 = rsum0 * fac0 + sum0;
        rsum1 = rsum1 * fac1 + sum1;
#pragma unroll
        for (int dt = 0; dt < 8; dt++) {
            accO[dt][0] *= fac0; accO[dt][1] *= fac0;
            accO[dt][2] *= fac1; accO[dt][3] *= fac1;
        }

        // O += P V : P transposed to A-frag via shuffles (no smem round-trip)
        int sA = (lane & ~3) | (t >> 1);
        int sB = sA + 2;
        bool odd = (t & 1);
#pragma unroll
        for (int ks = 0; ks < 8; ks++) {
            float p0 = s[ks][0], p1 = s[ks][1], p2 = s[ks][2], p3 = s[ks][3];
            float e0 = __shfl_sync(0xffffffffu, p0, sA);
            float e1 = __shfl_sync(0xffffffffu, p1, sA);
            float e2 = __shfl_sync(0xffffffffu, p2, sA);
            float e3 = __shfl_sync(0xffffffffu, p3, sA);
            float f0 = __shfl_sync(0xffffffffu, p0, sB);
            float f1 = __shfl_sync(0xffffffffu, p1, sB);
            float f2 = __shfl_sync(0xffffffffu, p2, sB);
            float f3 = __shfl_sync(0xffffffffu, p3, sB);
            uint32_t a[4];
            a[0] = __float_as_uint(odd ? e1 : e0);
            a[1] = __float_as_uint(odd ? e3 : e2);
            a[2] = __float_as_uint(odd ? f1 : f0);
            a[3] = __float_as_uint(odd ? f3 : f2);
#pragma unroll
            for (int dt = 0; dt < 8; dt++) {
                uint32_t b[2];
                b[0] = __float_as_uint(Vb[(ks*8 + t    )*SV + dt*8 + gr]);
                b[1] = __float_as_uint(Vb[(ks*8 + t + 4)*SV + dt*8 + gr]);
                mma8(accO[dt], a, b);
            }
        }
        __syncthreads();
    }

    // write unnormalized partials + stats
    if (t == 0) {
        d_pstat[((size_t)sp * GG + g) * NN + n0 + row0] = make_float2(rmax0, rsum0);
        d_pstat[((size_t)sp * GG + g) * NN + n0 + row1] = make_float2(rmax1, rsum1);
    }
    float* po = d_po + (size_t)sp * NN * FEAT;
#pragma unroll
    for (int dt = 0; dt < 8; dt++) {
        int o = g*64 + dt*8 + 2*t;
        *(float2*)&po[(size_t)(n0 + row0) * FEAT + o] = make_float2(accO[dt][0], accO[dt][1]);
        *(float2*)&po[(size_t)(n0 + row1) * FEAT + o] = make_float2(accO[dt][2], accO[dt][3]);
    }
}

// ---------------- merge partials -> final output ----------------
__global__ __launch_bounds__(256)
void merge_kernel(const float* __restrict__ Wv_b, float* __restrict__ out)
{
    int idx = blockIdx.x * 256 + threadIdx.x;
    int n = idx >> 10, o = idx & 1023, g = o >> 6;
    float2 st[NSPLIT];
    float M = -1e30f;
#pragma unroll
    for (int s = 0; s < NSPLIT; s++) {
        st[s] = d_pstat[((size_t)s * GG + g) * NN + n];
        M = fmaxf(M, st[s].x);
    }
    float num = 0.0f, den = 0.0f;
#pragma unroll
    for (int s = 0; s < NSPLIT; s++) {
        float w = __expf(st[s].x - M);
        num += d_po[((size_t)s * NN + n) * FEAT + o] * w;
        den += st[s].y * w;
    }
    out[idx] = num / den + Wv_b[o];
}

// ---------------- launch ----------------
extern "C" void kernel_launch(void* const* d_in, const int* in_sizes, int n_in,
                              void* d_out, int out_size)
{
    const float* bbox     = (const float*)d_in[0];
    const float* ref_bbox = (const float*)d_in[1];
    const float* roi_feat = (const float*)d_in[2];
    const float* ref_feat = (const float*)d_in[3];
    const float* Wg_w     = (const float*)d_in[4];
    const float* Wg_b     = (const float*)d_in[5];
    const float* Wq_w     = (const float*)d_in[6];
    const float* Wq_b     = (const float*)d_in[7];
    const float* Wk_w     = (const float*)d_in[8];
    const float* Wk_b     = (const float*)d_in[9];
    const float* Wv_w     = (const float*)d_in[10];
    const float* Wv_b     = (const float*)d_in[11];
    const float* u        = (const float*)d_in[12];
    float* out = (float*)d_out;

    (void)in_sizes; (void)n_in; (void)out_size;

    static const int ATTN_SMEM = 2 * BUFSZ * 4;   // 71680 B
    cudaFuncSetAttribute(attn_split_kernel, cudaFuncAttributeMaxDynamicSharedMemorySize, ATTN_SMEM);

    prep_boxes_kernel<<<8, 256>>>(bbox, ref_bbox);
    w_kernel<<<dim3(MM / 128, NN), 128>>>(Wg_w, Wg_b);
    megagemm<<<dim3(16, 20), 256>>>(roi_feat, ref_feat, Wq_w, Wq_b,
                                    Wk_w, Wk_b, Wv_w, u);
    attn_split_kernel<<<dim3(NN / 64, GG, NSPLIT), 128, ATTN_SMEM>>>();
    merge_kernel<<<NN * FEAT / 256, 256>>>(Wv_b, out);
}